// round 5
// baseline (speedup 1.0000x reference)
#include <cuda_runtime.h>
#include <stdint.h>
#include <math.h>

#define MAXB 64
#define TPB 256
#define WPB (TPB / 32)

struct Meta {
    unsigned prefix[MAXB + 1]; // prefix of H*s_i^2 in output elements
    unsigned s[MAXB];
    unsigned s2[MAXB];
    unsigned ms[MAXB];   // magic multiplier for divide-by-s
    unsigned shs[MAXB];  // shift
    unsigned ms2[MAXB];  // magic multiplier for divide-by-s2
    unsigned shs2[MAXB]; // shift
};

__device__ Meta g_meta;

// Granlund-Montgomery round-up magic: q = (x*m) >> sh == x/d for x < 2^31, d >= 2.
__device__ __forceinline__ void magic_u32(unsigned d, unsigned& m, unsigned& sh) {
    unsigned k = 32u - __clz(d - 1u);
    unsigned long long two = 1ull << (31 + k);
    m = (unsigned)((two + d - 1ull) / d);
    sh = 31u + k;
}

__global__ void setup_kernel(const int* __restrict__ seq, const int* __restrict__ nh, int B) {
    if (threadIdx.x != 0 || blockIdx.x != 0) return;
    unsigned H = nh ? (unsigned)(*nh) : 16u;
    unsigned acc = 0;
    for (int i = 0; i < B; ++i) {
        unsigned s = (unsigned)seq[i];
        unsigned s2 = s * s;
        g_meta.prefix[i] = acc;
        g_meta.s[i] = s;
        g_meta.s2[i] = s2;
        magic_u32(s, g_meta.ms[i], g_meta.shs[i]);
        magic_u32(s2, g_meta.ms2[i], g_meta.shs2[i]);
        acc += H * s2;
    }
    g_meta.prefix[B] = acc;
}

__global__ void __launch_bounds__(TPB)
pack_kernel(const float* __restrict__ mask, float* __restrict__ out,
            unsigned out_size, unsigned nwarp, int B, unsigned S) {
    __shared__ unsigned sh_prefix[MAXB + 1];
    __shared__ unsigned sh_s[MAXB], sh_s2[MAXB];
    __shared__ unsigned sh_ms[MAXB], sh_shs[MAXB], sh_ms2[MAXB], sh_shs2[MAXB];

    for (int t = threadIdx.x; t <= B; t += TPB) sh_prefix[t] = g_meta.prefix[t];
    for (int t = threadIdx.x; t < B; t += TPB) {
        sh_s[t] = g_meta.s[t];     sh_s2[t] = g_meta.s2[t];
        sh_ms[t] = g_meta.ms[t];   sh_shs[t] = g_meta.shs[t];
        sh_ms2[t] = g_meta.ms2[t]; sh_shs2[t] = g_meta.shs2[t];
    }
    __syncthreads();

    unsigned w = blockIdx.x * WPB + (threadIdx.x >> 5);
    if (w >= nwarp) return;
    unsigned lane  = threadIdx.x & 31u;
    unsigned wbase = w * 128u;            // warp covers 128 consecutive floats

    // ---- warp-uniform decomposition at wbase (computed redundantly per lane;
    //      ptxas promotes to uniform datapath) ----
    int i = 0;
    while (i + 1 < B && wbase >= sh_prefix[i + 1]) ++i;
    unsigned pieceEnd = sh_prefix[i + 1];
    unsigned s  = sh_s[i];
    unsigned s2 = sh_s2[i];
    unsigned rem  = wbase - sh_prefix[i];
    unsigned h0   = (unsigned)(((unsigned long long)rem * sh_ms2[i]) >> sh_shs2[i]);
    unsigned pos0 = rem - h0 * s2;        // position inside the s*s block
    unsigned r0   = (unsigned)(((unsigned long long)pos0 * sh_ms[i]) >> sh_shs[i]);
    unsigned c0   = pos0 - r0 * s;

    // ---- per-lane derivation: s >= 128 so a warp spans at most 2 rows ----
    unsigned base_l = wbase + 4u * lane;
    unsigned cl = c0 + 4u * lane;
    unsigned rl = r0;
    if (cl >= s) {                        // wrapped into next row (maybe next head)
        cl -= s;
        rl = r0 + 1u;
        if (rl == s) rl = 0u;             // head boundary: source repeats from row 0
    }

    bool fast = (base_l + 4u <= pieceEnd) && (cl + 4u <= s) && (base_l + 4u <= out_size);

    if (fast) {
        const float* row = mask + ((size_t)i * S + rl) * (size_t)S;
        float4 R;
        unsigned a = cl & 3u;
        if (a == 0u) {
            R = *reinterpret_cast<const float4*>(row + cl);      // aligned LDG.128
        } else {
            // two aligned LDG.128 window loads; in-bounds since s < S
            unsigned cb = cl & ~3u;
            float4 W0 = *reinterpret_cast<const float4*>(row + cb);
            float4 W1 = *reinterpret_cast<const float4*>(row + cb + 4u);
            R.x = (a == 1u) ? W0.y : (a == 2u) ? W0.z : W0.w;
            R.y = (a == 1u) ? W0.z : (a == 2u) ? W0.w : W1.x;
            R.z = (a == 1u) ? W0.w : (a == 2u) ? W1.x : W1.y;
            R.w = (a == 1u) ? W1.x : (a == 2u) ? W1.y : W1.z;
        }
        *reinterpret_cast<float4*>(out + base_l) = R;            // aligned STG.128
    } else {
        // slow path: row straddle / piece boundary / tail — scalar per element
        for (unsigned j = 0; j < 4u; ++j) {
            unsigned idx = base_l + j;
            if (idx >= out_size) break;
            int ii = i;
            while (ii + 1 < B && idx >= sh_prefix[ii + 1]) ++ii;
            unsigned rem2 = idx - sh_prefix[ii];
            unsigned ss  = sh_s[ii];
            unsigned ss2 = sh_s2[ii];
            unsigned hh  = (unsigned)(((unsigned long long)rem2 * sh_ms2[ii]) >> sh_shs2[ii]);
            unsigned p2  = rem2 - hh * ss2;
            unsigned rr  = (unsigned)(((unsigned long long)p2 * sh_ms[ii]) >> sh_shs[ii]);
            unsigned cc  = p2 - rr * ss;
            out[idx] = mask[((size_t)ii * S + rr) * (size_t)S + cc];
        }
    }
}

extern "C" void kernel_launch(void* const* d_in, const int* in_sizes, int n_in,
                              void* d_out, int out_size) {
    const float* mask = (const float*)d_in[0];
    const int* seq = (const int*)d_in[1];
    const int* nh = (n_in >= 3) ? (const int*)d_in[2] : nullptr;

    int B = in_sizes[1];
    if (B > MAXB) B = MAXB;
    long long SS = (long long)in_sizes[0] / (B > 0 ? B : 1);
    unsigned S = (unsigned)(sqrt((double)SS) + 0.5);

    setup_kernel<<<1, 32>>>(seq, nh, B);

    unsigned osz = (unsigned)out_size;
    unsigned nwarp = (osz + 127u) / 128u;
    if (nwarp == 0) return;
    unsigned grid = (nwarp + WPB - 1) / WPB;
    pack_kernel<<<grid, TPB>>>(mask, (float*)d_out, osz, nwarp, B, S);
}

// round 6
// speedup vs baseline: 1.0711x; 1.0711x over previous
#include <cuda_runtime.h>
#include <stdint.h>
#include <math.h>

#define MAXB 64
#define TPB 256
#define HMAX 16

struct Meta {
    unsigned prefix[MAXB + 1]; // prefix of H*s_i^2 in output elements
    unsigned s[MAXB];
    unsigned s2[MAXB];
    unsigned H;
};

__device__ Meta g_meta;

__global__ void setup_kernel(const int* __restrict__ seq, const int* __restrict__ nh, int B) {
    if (threadIdx.x != 0 || blockIdx.x != 0) return;
    unsigned H = nh ? (unsigned)(*nh) : 16u;
    g_meta.H = H;
    unsigned acc = 0;
    for (int i = 0; i < B; ++i) {
        unsigned s = (unsigned)seq[i];
        unsigned s2 = s * s;
        g_meta.prefix[i] = acc;
        g_meta.s[i] = s;
        g_meta.s2[i] = s2;
        acc += H * s2;
    }
    g_meta.prefix[B] = acc;
}

// One CTA per (batch, head, row). Source row is contiguous & 16B-aligned;
// destination run is contiguous with block-uniform misalignment.
__global__ void __launch_bounds__(TPB)
copy_rows_kernel(const float* __restrict__ mask, float* __restrict__ out,
                 unsigned out_size, unsigned S) {
    const unsigned i = blockIdx.z;
    const unsigned h = blockIdx.y;
    const unsigned r = blockIdx.x;

    if (h >= g_meta.H) return;
    unsigned s = g_meta.s[i];
    if (r >= s) return;

    unsigned off = g_meta.prefix[i] + h * g_meta.s2[i] + r * s;
    if (off >= out_size) return;
    if (s > out_size - off) s = out_size - off;   // safety clamp

    const float* __restrict__ src = mask + ((size_t)i * S + r) * (size_t)S;
    float*       __restrict__ dst = out + off;

    const unsigned t = threadIdx.x;
    unsigned lead = (4u - (off & 3u)) & 3u;       // bring dst to 16B alignment
    if (lead > s) lead = s;

    // scalar head
    if (t < lead) dst[t] = src[t];

    const unsigned n  = s - lead;
    const unsigned n4 = n >> 2;                   // aligned float4 stores
    float* vdst = dst + lead;
    const unsigned b = lead;                      // source misalign == lead (0..3)

    if (b == 0u) {
        const float4* vsrc = reinterpret_cast<const float4*>(src);
        float4*       vd   = reinterpret_cast<float4*>(vdst);
        for (unsigned k = t; k < n4; k += TPB)
            vd[k] = vsrc[k];                      // LDG.128 + STG.128
    } else {
        // window base = src (row-aligned). Overread <= 3 floats past s stays
        // inside the row since s <= S-1.
        const float4* wsrc = reinterpret_cast<const float4*>(src);
        float4*       vd   = reinterpret_cast<float4*>(vdst);
        for (unsigned k = t; k < n4; k += TPB) {
            float4 W0 = wsrc[k];
            float4 W1 = wsrc[k + 1u];
            float4 R;
            R.x = (b == 1u) ? W0.y : (b == 2u) ? W0.z : W0.w;
            R.y = (b == 1u) ? W0.z : (b == 2u) ? W0.w : W1.x;
            R.z = (b == 1u) ? W0.w : (b == 2u) ? W1.x : W1.y;
            R.w = (b == 1u) ? W1.x : (b == 2u) ? W1.y : W1.z;
            vd[k] = R;
        }
    }

    // scalar tail (< 4 elements)
    const unsigned done = lead + (n4 << 2);
    const unsigned rem  = s - done;
    if (t < rem) dst[done + t] = src[done + t];
}

extern "C" void kernel_launch(void* const* d_in, const int* in_sizes, int n_in,
                              void* d_out, int out_size) {
    const float* mask = (const float*)d_in[0];
    const int* seq = (const int*)d_in[1];
    const int* nh = (n_in >= 3) ? (const int*)d_in[2] : nullptr;

    int B = in_sizes[1];
    if (B > MAXB) B = MAXB;
    long long SS = (long long)in_sizes[0] / (B > 0 ? B : 1);
    unsigned S = (unsigned)(sqrt((double)SS) + 0.5);

    setup_kernel<<<1, 32>>>(seq, nh, B);

    if (out_size <= 0) return;
    dim3 grid(S, HMAX, (unsigned)B);
    copy_rows_kernel<<<grid, TPB>>>(mask, (float*)d_out, (unsigned)out_size, S);
}